// round 4
// baseline (speedup 1.0000x reference)
#include <cuda_runtime.h>
#include <cstdint>
#include <math.h>

#define ALPHA 1000.0f
#define NB 8192
#define ND 784
#define NH 256
#define NE 32
#define NK 512

// scratch (allocation-free rule: __device__ globals)
__device__ float g_h [NB * NH];
__device__ float g_h2[NB * NH];

// ---------------------------------------------------------------------------
// tf32 helpers (baseline PTX, sm_80+)
// ---------------------------------------------------------------------------
__device__ __forceinline__ uint32_t tf32_round(float x) {
    uint32_t u;
    asm("cvt.rna.tf32.f32 %0, %1;" : "=r"(u) : "f"(x));
    return u;
}

__device__ __forceinline__ void mma_tf32(float* d, const uint32_t* a, const uint32_t* b) {
    asm volatile(
        "mma.sync.aligned.m16n8k8.row.col.f32.tf32.tf32.f32 "
        "{%0,%1,%2,%3}, {%4,%5,%6,%7}, {%8,%9}, {%0,%1,%2,%3};"
        : "+f"(d[0]), "+f"(d[1]), "+f"(d[2]), "+f"(d[3])
        : "r"(a[0]), "r"(a[1]), "r"(a[2]), "r"(a[3]), "r"(b[0]), "r"(b[1]));
}

// ---------------------------------------------------------------------------
// 3xTF32 tensor-core GEMM: C[M,N] = A[M,K] @ W[K,N] + bias (+ReLU).
// CTA tile 128x128, K chunks of 32. 256 threads = 8 warps (2 M x 4 N),
// warp tile 64x32 (4 x 4 m16n8 tiles).
// Smem holds fragment-major hi/lo operand blocks:
//   A block (mt,ks): 32 lanes x 16B (a0..a3);  B block (nt,ks): 32 lanes x 8B.
// All LDS/STS conflict-free. Requires M % 128 == 0; N, K arbitrary (guarded).
// ---------------------------------------------------------------------------
#define SA_HI 0
#define SA_LO 16384
#define SB_HI 32768
#define SB_LO 49152
#define GEMM_SMEM 65536

template <bool RELU>
__global__ __launch_bounds__(256) void mma_gemm(
    const float* __restrict__ A, const float* __restrict__ W,
    const float* __restrict__ bias, float* __restrict__ C,
    int M, int N, int K)
{
    extern __shared__ char smem[];
    char* sAhi = smem + SA_HI;
    char* sAlo = smem + SA_LO;
    char* sBhi = smem + SB_HI;
    char* sBlo = smem + SB_LO;

    const int tid  = threadIdx.x;
    const int wid  = tid >> 5;
    const int lane = tid & 31;
    const int wm   = wid & 1;    // 0..1 (M halves of 64)
    const int wn   = wid >> 1;   // 0..3 (N quarters of 32)
    const int g    = lane >> 2;  // fragment group id
    const int c    = lane & 3;   // thread-in-group

    const int m0 = blockIdx.y * 128;
    const int n0 = blockIdx.x * 128;

    float acc[4][4][4];
#pragma unroll
    for (int mt = 0; mt < 4; mt++)
#pragma unroll
        for (int nt = 0; nt < 4; nt++)
#pragma unroll
            for (int i = 0; i < 4; i++) acc[mt][nt][i] = 0.f;

    const int nch = (K + 31) / 32;
    for (int t = 0; t < nch; t++) {
        const int k0 = t * 32;

        // ---- stage A: 32 blocks (mt 0..7, ks 0..3) x 32 lanes, hi/lo ----
#pragma unroll
        for (int i = 0; i < 4; i++) {
            const int slot = tid + i * 256;       // 0..1023
            const int blk  = slot >> 5;
            const int ln   = slot & 31;
            const int mt   = blk >> 2;
            const int ks   = blk & 3;
            const int gg   = ln >> 2;
            const int cc   = ln & 3;
            const int row  = m0 + mt * 16 + gg;
            const int k    = k0 + ks * 8 + cc;
            float v0 = 0.f, v1 = 0.f, v2 = 0.f, v3 = 0.f;
            if (k < K) {
                v0 = A[(size_t)row * K + k];
                v1 = A[(size_t)(row + 8) * K + k];
            }
            if (k + 4 < K) {
                v2 = A[(size_t)row * K + k + 4];
                v3 = A[(size_t)(row + 8) * K + k + 4];
            }
            uint4 hi, lo;
            hi.x = tf32_round(v0); lo.x = tf32_round(v0 - __uint_as_float(hi.x));
            hi.y = tf32_round(v1); lo.y = tf32_round(v1 - __uint_as_float(hi.y));
            hi.z = tf32_round(v2); lo.z = tf32_round(v2 - __uint_as_float(hi.z));
            hi.w = tf32_round(v3); lo.w = tf32_round(v3 - __uint_as_float(hi.w));
            *(uint4*)(sAhi + slot * 16) = hi;
            *(uint4*)(sAlo + slot * 16) = lo;
        }

        // ---- stage B: 64 blocks (nt 0..15, ks 0..3) x 32 lanes, hi/lo ----
#pragma unroll
        for (int i = 0; i < 8; i++) {
            const int slot = tid + i * 256;       // 0..2047
            const int blk  = slot >> 5;
            const int ln   = slot & 31;
            const int nt   = blk >> 2;
            const int ks   = blk & 3;
            const int gg   = ln >> 2;
            const int cc   = ln & 3;
            const int n    = n0 + nt * 8 + gg;
            const int k    = k0 + ks * 8 + cc;
            float b0 = 0.f, b1 = 0.f;
            if (n < N) {
                if (k < K)     b0 = W[(size_t)k * N + n];
                if (k + 4 < K) b1 = W[(size_t)(k + 4) * N + n];
            }
            uint2 hi, lo;
            hi.x = tf32_round(b0); lo.x = tf32_round(b0 - __uint_as_float(hi.x));
            hi.y = tf32_round(b1); lo.y = tf32_round(b1 - __uint_as_float(hi.y));
            *(uint2*)(sBhi + slot * 8) = hi;
            *(uint2*)(sBlo + slot * 8) = lo;
        }
        __syncthreads();

        // ---- compute: 4 k-steps, 16 tiles, 3 mma each ----
#pragma unroll
        for (int ks = 0; ks < 4; ks++) {
            uint4 ah[4], al[4];
#pragma unroll
            for (int mt = 0; mt < 4; mt++) {
                const int blk = ((wm * 4 + mt) * 4 + ks) * 32 + lane;
                ah[mt] = *(const uint4*)(sAhi + blk * 16);
                al[mt] = *(const uint4*)(sAlo + blk * 16);
            }
            uint2 bh[4], bl[4];
#pragma unroll
            for (int nt = 0; nt < 4; nt++) {
                const int blk = ((wn * 4 + nt) * 4 + ks) * 32 + lane;
                bh[nt] = *(const uint2*)(sBhi + blk * 8);
                bl[nt] = *(const uint2*)(sBlo + blk * 8);
            }
#pragma unroll
            for (int mt = 0; mt < 4; mt++)
#pragma unroll
                for (int nt = 0; nt < 4; nt++) {
                    mma_tf32(acc[mt][nt], (const uint32_t*)&ah[mt], (const uint32_t*)&bh[nt]);
                    mma_tf32(acc[mt][nt], (const uint32_t*)&ah[mt], (const uint32_t*)&bl[nt]);
                    mma_tf32(acc[mt][nt], (const uint32_t*)&al[mt], (const uint32_t*)&bh[nt]);
                }
        }
        __syncthreads();
    }

    // ---- epilogue: bias + relu, direct float2 stores ----
#pragma unroll
    for (int nt = 0; nt < 4; nt++) {
        const int col = n0 + (wn * 4 + nt) * 8 + 2 * c;
        if (col < N) {
            const float bx = __ldg(&bias[col]);
            const float by = __ldg(&bias[col + 1]);
#pragma unroll
            for (int mt = 0; mt < 4; mt++) {
                const int row = m0 + (wm * 4 + mt) * 16 + g;
                float2 lo_v, hi_v;
                lo_v.x = acc[mt][nt][0] + bx;
                lo_v.y = acc[mt][nt][1] + by;
                hi_v.x = acc[mt][nt][2] + bx;
                hi_v.y = acc[mt][nt][3] + by;
                if (RELU) {
                    lo_v.x = fmaxf(lo_v.x, 0.f); lo_v.y = fmaxf(lo_v.y, 0.f);
                    hi_v.x = fmaxf(hi_v.x, 0.f); hi_v.y = fmaxf(hi_v.y, 0.f);
                }
                *(float2*)&C[(size_t)row * N + col]       = lo_v;
                *(float2*)&C[(size_t)(row + 8) * N + col] = hi_v;
            }
        }
    }
}

// ---------------------------------------------------------------------------
// Fused distances + stable softmin (unchanged, ~25us).
// ---------------------------------------------------------------------------
#define REPS_STRIDE 36
#define DIST_SMEM_FLOATS (NK * REPS_STRIDE + 16 * NE + 256 + 32)

__global__ __launch_bounds__(256) void dist_softmin_kernel(
    const float* __restrict__ emb, const float* __restrict__ reps,
    float* __restrict__ weighted, float* __restrict__ distances)
{
    extern __shared__ float s[];
    float* reps_s = s;
    float* emb_s  = s + NK * REPS_STRIDE;
    float* red    = emb_s + 16 * NE;
    float* rmin   = red + 256;
    float* rsum   = rmin + 16;

    const int tid  = threadIdx.x;
    const int brow = blockIdx.x * 16;

    const float4* repsg = (const float4*)reps;
    for (int idx = tid; idx < NK * NE / 4; idx += 256) {
        const int k  = idx >> 3;
        const int e4 = idx & 7;
        ((float4*)&reps_s[k * REPS_STRIDE])[e4] = repsg[idx];
    }
    const float4* embg = (const float4*)(emb + (size_t)brow * NE);
    for (int idx = tid; idx < 16 * NE / 4; idx += 256)
        ((float4*)emb_s)[idx] = embg[idx];
    __syncthreads();

    const int row  = tid >> 4;
    const int lane = tid & 15;

    float er[NE];
#pragma unroll
    for (int e = 0; e < NE; e++) er[e] = emb_s[row * NE + e];

    float pd[32];
    float pmin = 3.4e38f;
#pragma unroll
    for (int j = 0; j < 32; j++) {
        const int k = j * 16 + lane;
        const float4* rp = (const float4*)&reps_s[k * REPS_STRIDE];
        float acc = 0.f;
#pragma unroll
        for (int e4 = 0; e4 < 8; e4++) {
            float4 r4 = rp[e4];
            float d0 = er[e4 * 4 + 0] - r4.x;
            float d1 = er[e4 * 4 + 1] - r4.y;
            float d2 = er[e4 * 4 + 2] - r4.z;
            float d3 = er[e4 * 4 + 3] - r4.w;
            acc += d0 * d0; acc += d1 * d1; acc += d2 * d2; acc += d3 * d3;
        }
        pd[j] = acc;
        pmin = fminf(pmin, acc);
    }

    red[tid] = pmin;
    __syncthreads();
    if (lane == 0) {
        float m = red[row * 16];
#pragma unroll
        for (int t = 1; t < 16; t++) m = fminf(m, red[row * 16 + t]);
        rmin[row] = m;
    }
    __syncthreads();
    const float mv = rmin[row];

    float pe[32];
    float psum = 0.f;
#pragma unroll
    for (int j = 0; j < 32; j++) {
        pe[j] = expf(-ALPHA * (pd[j] - mv));
        psum += pe[j];
    }
    red[tid] = psum;
    __syncthreads();
    if (lane == 0) {
        float su = 0.f;
#pragma unroll
        for (int t = 0; t < 16; t++) su += red[row * 16 + t];
        rsum[row] = su;
    }
    __syncthreads();
    const float inv = 1.0f / rsum[row];

    const size_t base = (size_t)(brow + row) * NK;
#pragma unroll
    for (int j = 0; j < 32; j++) {
        const int k = j * 16 + lane;
        const float dv = pd[j];
        distances[base + k] = dv;
        weighted[base + k]  = dv * pe[j] * inv;
    }
}

// ---------------------------------------------------------------------------
extern "C" void kernel_launch(void* const* d_in, const int* in_sizes, int n_in,
                              void* d_out, int out_size)
{
    const float* x    = (const float*)d_in[0];
    const float* reps = (const float*)d_in[1];
    const float* W1   = (const float*)d_in[2];
    const float* b1   = (const float*)d_in[3];
    const float* W2   = (const float*)d_in[4];
    const float* b2   = (const float*)d_in[5];
    const float* W3   = (const float*)d_in[6];
    const float* b3   = (const float*)d_in[7];
    const float* W4   = (const float*)d_in[8];
    const float* b4   = (const float*)d_in[9];

    float* out       = (float*)d_out;
    float* weighted  = out;
    float* distances = out + (size_t)NB * NK;
    float* rec       = out + 2 * (size_t)NB * NK;
    float* emb       = out + 2 * (size_t)NB * NK + (size_t)NB * ND;

    float *hbuf, *h2buf;
    cudaGetSymbolAddress((void**)&hbuf,  g_h);
    cudaGetSymbolAddress((void**)&h2buf, g_h2);

    cudaFuncSetAttribute(mma_gemm<true>,
                         cudaFuncAttributeMaxDynamicSharedMemorySize, GEMM_SMEM);
    cudaFuncSetAttribute(mma_gemm<false>,
                         cudaFuncAttributeMaxDynamicSharedMemorySize, GEMM_SMEM);
    const int dist_smem = DIST_SMEM_FLOATS * (int)sizeof(float);
    cudaFuncSetAttribute(dist_softmin_kernel,
                         cudaFuncAttributeMaxDynamicSharedMemorySize, dist_smem);

    // h = relu(x @ W1 + b1)           [8192,784] @ [784,256]
    mma_gemm<true ><<<dim3(2, NB / 128), 256, GEMM_SMEM>>>(x, W1, b1, hbuf, NB, NH, ND);
    // emb = h @ W2 + b2               [8192,256] @ [256,32]
    mma_gemm<false><<<dim3(1, NB / 128), 256, GEMM_SMEM>>>(hbuf, W2, b2, emb, NB, NE, NH);
    // h2 = relu(emb @ W3 + b3)        [8192,32] @ [32,256]
    mma_gemm<true ><<<dim3(2, NB / 128), 256, GEMM_SMEM>>>(emb, W3, b3, h2buf, NB, NH, NE);
    // rec = h2 @ W4 + b4              [8192,256] @ [256,784]
    mma_gemm<false><<<dim3(7, NB / 128), 256, GEMM_SMEM>>>(h2buf, W4, b4, rec, NB, ND, NH);
    // distances + softmin
    dist_softmin_kernel<<<NB / 16, 256, dist_smem>>>(emb, reps, weighted, distances);
}